// round 2
// baseline (speedup 1.0000x reference)
#include <cuda_runtime.h>
#include <cstdint>
#include <cstddef>

// Problem constants (AttDecoder: B=64, H=512, E=300, VQ=32000, T=32 -> 33 steps)
#define BSZ   64
#define HID   512
#define EMBD  300
#define VQ    32000
#define STEPS 33
#define NBLK_L 250            // logits grid: 250 blocks x 128 cols

// ---------------------------------------------------------------------------
// Device scratch (no allocations allowed -> __device__ globals)
// h stored transposed + k-pair interleaved: pair p, batch b ->
//   float2 at hT2[p*BSZ + b]  (i.e. floats [(p*BSZ+b)*2 + {0,1}])
// ---------------------------------------------------------------------------
__device__ __align__(16) float g_hT2f[2][(HID/2) * BSZ * 2];  // double buffer
__device__ __align__(16) float g_xT2f[(EMBD/2) * BSZ * 2];    // relu(emb[idx])
__device__ __align__(16) float g_c[HID * BSZ];                // cell state [u][b]
__device__ float g_psum[BSZ * 256];                           // exp-sum partials
__device__ unsigned long long g_amax[BSZ];                    // packed argmax
__device__ float g_lse[BSZ];

// ---------------------------------------------------------------------------
// helpers
// ---------------------------------------------------------------------------
__device__ __forceinline__ unsigned long long ffma2(unsigned long long a,
                                                    unsigned long long b,
                                                    unsigned long long c) {
    unsigned long long d;
    asm("fma.rn.f32x2 %0, %1, %2, %3;" : "=l"(d) : "l"(a), "l"(b), "l"(c));
    return d;
}

__device__ __forceinline__ float2 u2f(unsigned long long u) {
    float2 f;
    asm("mov.b64 {%0,%1}, %2;" : "=f"(f.x), "=f"(f.y) : "l"(u));
    return f;
}

// monotonic float packing; ties resolve to LOWEST column (matches jnp.argmax)
__device__ __forceinline__ unsigned long long packmax(float v, int col) {
    unsigned int b = __float_as_uint(v);
    b = (b & 0x80000000u) ? ~b : (b | 0x80000000u);
    return ((unsigned long long)b << 32) | (unsigned long long)(0xFFFFFFFFu - (unsigned)col);
}

__device__ __forceinline__ float sigm(float x) { return 1.0f / (1.0f + expf(-x)); }

// ---------------------------------------------------------------------------
// INIT: h0 = q_att (transposed-pair layout), c0 = 0,
//       x0 = relu(emb[qix_to_aix[SOS=1]]), amax = 0
// ---------------------------------------------------------------------------
__global__ void k_init(const float* __restrict__ q_att,
                       const float* __restrict__ emb,
                       const int*   __restrict__ qix) {
    int gid = blockIdx.x * 256 + threadIdx.x;
    if (gid < BSZ * HID) {
        int b = gid & 63, u = gid >> 6;
        g_hT2f[0][((u >> 1) * BSZ + b) * 2 + (u & 1)] = q_att[b * HID + u];
    } else if (gid < 2 * BSZ * HID) {
        g_c[gid - BSZ * HID] = 0.0f;
    } else if (gid < 2 * BSZ * HID + BSZ * EMBD) {
        int i = gid - 2 * BSZ * HID;
        int b = i & 63, e = i >> 6;
        int nidx = __ldg(&qix[1]);
        float x = emb[(size_t)nidx * EMBD + e];
        g_xT2f[((e >> 1) * BSZ + b) * 2 + (e & 1)] = fmaxf(x, 0.0f);
    } else if (gid < 2 * BSZ * HID + BSZ * EMBD + BSZ) {
        g_amax[gid - 2 * BSZ * HID - BSZ * EMBD] = 0ull;
    }
}

// ---------------------------------------------------------------------------
// CELL: gates = x @ W_ih^T + h @ W_hh^T + (b_ih+b_hh); LSTM pointwise update.
// Grid 64 x 256. Block handles 8 hidden units (x4 gates = 32 cols).
// Warp w owns cols w*4..w*4+3; lanes = batches (l, l+32). f32x2 over K-pairs.
// Reads h buffer rb, writes h buffer rb^1.
// ---------------------------------------------------------------------------
__global__ void __launch_bounds__(256, 4)
k_cell(const float* __restrict__ W_ih, const float* __restrict__ W_hh,
       const float* __restrict__ b_ih, const float* __restrict__ b_hh, int rb) {
    int tid = threadIdx.x, w = tid >> 5, l = tid & 31;
    int u0 = blockIdx.x * 8;

    int j[4];
    const ulonglong2* wih[4];
    const ulonglong2* whh[4];
#pragma unroll
    for (int i = 0; i < 4; i++) {
        int cl = w * 4 + i;
        int gate = cl >> 3, uoff = cl & 7;
        j[i] = gate * HID + u0 + uoff;
        wih[i] = (const ulonglong2*)(W_ih + (size_t)j[i] * EMBD);
        whh[i] = (const ulonglong2*)(W_hh + (size_t)j[i] * HID);
    }

    unsigned long long acc[4][2];
#pragma unroll
    for (int i = 0; i < 4; i++) { acc[i][0] = 0ull; acc[i][1] = 0ull; }

    const unsigned long long* xu = (const unsigned long long*)g_xT2f;
#pragma unroll 2
    for (int k4 = 0; k4 < EMBD / 4; k4++) {
        unsigned long long a0 = xu[(2 * k4) * BSZ + l];
        unsigned long long a1 = xu[(2 * k4) * BSZ + l + 32];
        unsigned long long p0 = xu[(2 * k4 + 1) * BSZ + l];
        unsigned long long p1 = xu[(2 * k4 + 1) * BSZ + l + 32];
#pragma unroll
        for (int i = 0; i < 4; i++) {
            ulonglong2 wv = wih[i][k4];
            acc[i][0] = ffma2(wv.x, a0, acc[i][0]);
            acc[i][0] = ffma2(wv.y, p0, acc[i][0]);
            acc[i][1] = ffma2(wv.x, a1, acc[i][1]);
            acc[i][1] = ffma2(wv.y, p1, acc[i][1]);
        }
    }

    const unsigned long long* hu = (const unsigned long long*)g_hT2f[rb];
#pragma unroll 2
    for (int k4 = 0; k4 < HID / 4; k4++) {
        unsigned long long a0 = hu[(2 * k4) * BSZ + l];
        unsigned long long a1 = hu[(2 * k4) * BSZ + l + 32];
        unsigned long long p0 = hu[(2 * k4 + 1) * BSZ + l];
        unsigned long long p1 = hu[(2 * k4 + 1) * BSZ + l + 32];
#pragma unroll
        for (int i = 0; i < 4; i++) {
            ulonglong2 wv = whh[i][k4];
            acc[i][0] = ffma2(wv.x, a0, acc[i][0]);
            acc[i][0] = ffma2(wv.y, p0, acc[i][0]);
            acc[i][1] = ffma2(wv.x, a1, acc[i][1]);
            acc[i][1] = ffma2(wv.y, p1, acc[i][1]);
        }
    }

    __shared__ float sg[32][BSZ];
#pragma unroll
    for (int i = 0; i < 4; i++) {
        float bias = __ldg(&b_ih[j[i]]) + __ldg(&b_hh[j[i]]);
        float2 f0 = u2f(acc[i][0]);
        float2 f1 = u2f(acc[i][1]);
        int cl = w * 4 + i;
        sg[cl][l]      = f0.x + f0.y + bias;
        sg[cl][l + 32] = f1.x + f1.y + bias;
    }
    __syncthreads();

    float* hOut = g_hT2f[rb ^ 1];
    for (int e = tid; e < 8 * BSZ; e += 256) {
        int b = e & 63, uo = e >> 6;
        float iv = sg[uo][b];
        float fv = sg[8 + uo][b];
        float gv = sg[16 + uo][b];
        float ov = sg[24 + uo][b];
        int u = u0 + uo;
        float cO = g_c[u * BSZ + b];
        float cN = sigm(fv) * cO + sigm(iv) * tanhf(gv);
        float hN = sigm(ov) * tanhf(cN);
        g_c[u * BSZ + b] = cN;
        hOut[((u >> 1) * BSZ + b) * 2 + (u & 1)] = hN;
    }
}

// ---------------------------------------------------------------------------
// LOGITS: logits = h @ out_W^T + out_b (64 x 32000), writes raw logits into
// d_out slice for step t, accumulates per-block exp-sums and a packed atomic
// argmax. Grid 250 x 256; warp owns 16 vocab cols, lanes = batches (l, l+32).
// ---------------------------------------------------------------------------
__global__ void __launch_bounds__(256, 2)
k_logits(const float* __restrict__ out_W, const float* __restrict__ out_b,
         int hb, float* __restrict__ out, int t) {
    __shared__ float s_sum[8][BSZ];
    __shared__ unsigned long long s_max[8][BSZ];

    int tid = threadIdx.x, w = tid >> 5, l = tid & 31;
    int colBase = blockIdx.x * 128 + w * 16;
    const float* wbase = out_W + (size_t)colBase * HID;

    unsigned long long acc0[16], acc1[16];
#pragma unroll
    for (int c = 0; c < 16; c++) { acc0[c] = 0ull; acc1[c] = 0ull; }

    const unsigned long long* hu = (const unsigned long long*)g_hT2f[hb];
#pragma unroll 2
    for (int k4 = 0; k4 < HID / 4; k4++) {
        unsigned long long a0 = hu[(2 * k4) * BSZ + l];
        unsigned long long a1 = hu[(2 * k4) * BSZ + l + 32];
        unsigned long long p0 = hu[(2 * k4 + 1) * BSZ + l];
        unsigned long long p1 = hu[(2 * k4 + 1) * BSZ + l + 32];
        const ulonglong2* wp = (const ulonglong2*)(wbase + k4 * 4);
#pragma unroll
        for (int c = 0; c < 16; c++) {
            ulonglong2 wv = wp[c * (HID / 4)];   // row stride 512 floats (imm offset)
            acc0[c] = ffma2(wv.x, a0, acc0[c]);
            acc0[c] = ffma2(wv.y, p0, acc0[c]);
            acc1[c] = ffma2(wv.x, a1, acc1[c]);
            acc1[c] = ffma2(wv.y, p1, acc1[c]);
        }
    }

    int b0 = l, b1 = l + 32;
    float r0[16], r1[16];
    float es0 = 0.0f, es1 = 0.0f;
    unsigned long long m0 = 0ull, m1 = 0ull;
#pragma unroll
    for (int c = 0; c < 16; c++) {
        float bias = __ldg(&out_b[colBase + c]);
        float2 f0 = u2f(acc0[c]);
        float2 f1 = u2f(acc1[c]);
        r0[c] = f0.x + f0.y + bias;
        r1[c] = f1.x + f1.y + bias;
        es0 += __expf(r0[c]);
        es1 += __expf(r1[c]);
        unsigned long long q0 = packmax(r0[c], colBase + c);
        unsigned long long q1 = packmax(r1[c], colBase + c);
        m0 = (q0 > m0) ? q0 : m0;
        m1 = (q1 > m1) ? q1 : m1;
    }

    float* o0 = out + ((size_t)b0 * STEPS + t) * VQ + colBase;
    float* o1 = out + ((size_t)b1 * STEPS + t) * VQ + colBase;
#pragma unroll
    for (int c4 = 0; c4 < 4; c4++) {
        *(float4*)(o0 + c4 * 4) = make_float4(r0[c4*4], r0[c4*4+1], r0[c4*4+2], r0[c4*4+3]);
        *(float4*)(o1 + c4 * 4) = make_float4(r1[c4*4], r1[c4*4+1], r1[c4*4+2], r1[c4*4+3]);
    }

    s_sum[w][b0] = es0; s_sum[w][b1] = es1;
    s_max[w][b0] = m0;  s_max[w][b1] = m1;
    __syncthreads();

    if (tid < BSZ) {
        float s = 0.0f;
        unsigned long long m = 0ull;
#pragma unroll
        for (int ww = 0; ww < 8; ww++) {
            s += s_sum[ww][tid];
            unsigned long long q = s_max[ww][tid];
            m = (q > m) ? q : m;
        }
        g_psum[tid * 256 + blockIdx.x] = s;
        atomicMax(&g_amax[tid], m);
    }
}

// ---------------------------------------------------------------------------
// REDUCE + EMBED: per row: lse = log(sum of 250 partials); next token from
// packed argmax -> qix_to_aix -> relu(emb[next]) into xT2; reset amax.
// One block, 256 threads; warp w reduces rows w*8..w*8+7.
// ---------------------------------------------------------------------------
__global__ void k_reduce(const float* __restrict__ emb, const int* __restrict__ qix) {
    __shared__ int s_nidx[BSZ];
    int tid = threadIdx.x, w = tid >> 5, l = tid & 31;

    for (int rr = 0; rr < 8; rr++) {
        int r = w * 8 + rr;
        float s = 0.0f;
#pragma unroll
        for (int k = 0; k < 8; k++) {
            int idx = l + k * 32;
            if (idx < NBLK_L) s += g_psum[r * 256 + idx];
        }
#pragma unroll
        for (int off = 16; off > 0; off >>= 1)
            s += __shfl_xor_sync(0xFFFFFFFFu, s, off);
        if (l == 0) {
            g_lse[r] = logf(s);
            unsigned long long m = g_amax[r];
            int col = (int)(0xFFFFFFFFu - (unsigned)(m & 0xFFFFFFFFull));
            s_nidx[r] = __ldg(&qix[col]);
            g_amax[r] = 0ull;
        }
    }
    __syncthreads();

    for (int i = tid; i < BSZ * EMBD; i += 256) {
        int b = i & 63, e = i >> 6;
        float x = __ldg(&emb[(size_t)s_nidx[b] * EMBD + e]);
        g_xT2f[((e >> 1) * BSZ + b) * 2 + (e & 1)] = fmaxf(x, 0.0f);
    }
}

// ---------------------------------------------------------------------------
// SUB: out[b][t][:] -= lse[b]  (in place, float4). Grid 2000 x 256.
// ---------------------------------------------------------------------------
__global__ void k_sub(float* __restrict__ out, int t) {
    int gid = blockIdx.x * 256 + threadIdx.x;   // 512000 threads * 4 elems
    int idx = gid * 4;
    int b = idx / VQ;
    int v = idx - b * VQ;
    float lse = __ldg(&g_lse[b]);
    float4* p = (float4*)(out + ((size_t)b * STEPS + t) * VQ + v);
    float4 r = *p;
    r.x -= lse; r.y -= lse; r.z -= lse; r.w -= lse;
    *p = r;
}

// ---------------------------------------------------------------------------
// launch: init + 33 x (cell -> logits -> reduce -> sub), all graph nodes
// ---------------------------------------------------------------------------
extern "C" void kernel_launch(void* const* d_in, const int* in_sizes, int n_in,
                              void* d_out, int out_size) {
    (void)in_sizes; (void)n_in; (void)out_size;
    // inputs in setup_inputs order:
    // 0 input_h (unused), 1 q_att, 2 emb, 3 W_ih, 4 W_hh, 5 b_ih, 6 b_hh,
    // 7 out_W, 8 out_b, 9 qix_to_aix, (10 max_len, unused: T=32 fixed)
    const float* q_att = (const float*)d_in[1];
    const float* emb   = (const float*)d_in[2];
    const float* W_ih  = (const float*)d_in[3];
    const float* W_hh  = (const float*)d_in[4];
    const float* b_ih  = (const float*)d_in[5];
    const float* b_hh  = (const float*)d_in[6];
    const float* out_W = (const float*)d_in[7];
    const float* out_b = (const float*)d_in[8];
    const int*   qix   = (const int*)d_in[9];
    float* out = (float*)d_out;

    int initWork = 2 * BSZ * HID + BSZ * EMBD + BSZ;
    k_init<<<(initWork + 255) / 256, 256>>>(q_att, emb, qix);

    for (int t = 0; t < STEPS; t++) {
        int rb = t & 1;
        k_cell<<<64, 256>>>(W_ih, W_hh, b_ih, b_hh, rb);
        k_logits<<<NBLK_L, 256>>>(out_W, out_b, rb ^ 1, out, t);
        k_reduce<<<1, 256>>>(emb, qix);
        k_sub<<<(BSZ * VQ / 4 + 255) / 256, 256>>>(out, t);
    }
}

// round 4
// speedup vs baseline: 1.4478x; 1.4478x over previous
#include <cuda_runtime.h>
#include <cstdint>
#include <cstddef>

// AttDecoder: B=64, H=512, E=300, VQ=32000, 33 steps
#define BSZ    64
#define HID    512
#define EMBD   300
#define VQ     32000
#define STEPS  33
#define NBLK_L 500            // logits grid: 500 blocks x 64 cols
#define COLS_B 64             // cols per logits block
#define COLS_W 8              // cols per warp

// ---------------------------------------------------------------------------
// Device scratch. h transposed + k-pair interleaved:
//   pair p, batch b -> floats [(p*BSZ+b)*2 + {0,1}]
// ---------------------------------------------------------------------------
__device__ __align__(16) float g_hT2f[2][(HID/2) * BSZ * 2];  // double buffer
__device__ __align__(16) float g_xT2f[(EMBD/2) * BSZ * 2];    // relu(emb[idx])
__device__ __align__(16) float g_c[HID * BSZ];                // cell state [u][b]
__device__ float g_psum[BSZ * 512];                           // exp-sum partials
__device__ unsigned long long g_amax[BSZ];                    // packed argmax
__device__ float g_lse[BSZ];

// ---------------------------------------------------------------------------
__device__ __forceinline__ unsigned long long ffma2(unsigned long long a,
                                                    unsigned long long b,
                                                    unsigned long long c) {
    unsigned long long d;
    asm("fma.rn.f32x2 %0, %1, %2, %3;" : "=l"(d) : "l"(a), "l"(b), "l"(c));
    return d;
}

__device__ __forceinline__ float2 u2f(unsigned long long u) {
    float2 f;
    asm("mov.b64 {%0,%1}, %2;" : "=f"(f.x), "=f"(f.y) : "l"(u));
    return f;
}

// monotonic float packing; ties resolve to LOWEST column (matches jnp.argmax)
__device__ __forceinline__ unsigned long long packmax(float v, int col) {
    unsigned int b = __float_as_uint(v);
    b = (b & 0x80000000u) ? ~b : (b | 0x80000000u);
    return ((unsigned long long)b << 32) | (unsigned long long)(0xFFFFFFFFu - (unsigned)col);
}

__device__ __forceinline__ float sigm(float x) { return 1.0f / (1.0f + expf(-x)); }

// ---------------------------------------------------------------------------
// INIT: h0 = q_att (pair layout), c0 = 0, x0 = relu(emb[qix[SOS=1]]), amax = 0
// ---------------------------------------------------------------------------
__global__ void k_init(const float* __restrict__ q_att,
                       const float* __restrict__ emb,
                       const int*   __restrict__ qix) {
    int gid = blockIdx.x * 256 + threadIdx.x;
    if (gid < BSZ * HID) {
        int b = gid & 63, u = gid >> 6;
        g_hT2f[0][((u >> 1) * BSZ + b) * 2 + (u & 1)] = q_att[b * HID + u];
    } else if (gid < 2 * BSZ * HID) {
        g_c[gid - BSZ * HID] = 0.0f;
    } else if (gid < 2 * BSZ * HID + BSZ * EMBD) {
        int i = gid - 2 * BSZ * HID;
        int b = i & 63, e = i >> 6;
        int nidx = __ldg(&qix[1]);
        float x = emb[(size_t)nidx * EMBD + e];
        g_xT2f[((e >> 1) * BSZ + b) * 2 + (e & 1)] = fmaxf(x, 0.0f);
    } else if (gid < 2 * BSZ * HID + BSZ * EMBD + BSZ) {
        g_amax[gid - 2 * BSZ * HID - BSZ * EMBD] = 0ull;
    }
}

// ---------------------------------------------------------------------------
// CELL: gates = x @ W_ih^T + h @ W_hh^T + (b_ih+b_hh); LSTM pointwise update.
// Grid 64 x 256. Block = 8 hidden units (x4 gates = 32 cols). Warp w owns 4
// cols; lanes = batches (l, l+32). Reads h buf rb, writes rb^1.
// ---------------------------------------------------------------------------
__global__ void __launch_bounds__(256, 2)
k_cell(const float* __restrict__ W_ih, const float* __restrict__ W_hh,
       const float* __restrict__ b_ih, const float* __restrict__ b_hh, int rb) {
    int tid = threadIdx.x, w = tid >> 5, l = tid & 31;
    int u0 = blockIdx.x * 8;

    int j[4];
    const ulonglong2* wih[4];
    const ulonglong2* whh[4];
#pragma unroll
    for (int i = 0; i < 4; i++) {
        int cl = w * 4 + i;
        int gate = cl >> 3, uoff = cl & 7;
        j[i] = gate * HID + u0 + uoff;
        wih[i] = (const ulonglong2*)(W_ih + (size_t)j[i] * EMBD);
        whh[i] = (const ulonglong2*)(W_hh + (size_t)j[i] * HID);
    }

    unsigned long long acc[4][2];
#pragma unroll
    for (int i = 0; i < 4; i++) { acc[i][0] = 0ull; acc[i][1] = 0ull; }

    const unsigned long long* xu = (const unsigned long long*)g_xT2f;
#pragma unroll 3
    for (int k4 = 0; k4 < EMBD / 4; k4++) {
        unsigned long long a0 = xu[(2 * k4) * BSZ + l];
        unsigned long long a1 = xu[(2 * k4) * BSZ + l + 32];
        unsigned long long p0 = xu[(2 * k4 + 1) * BSZ + l];
        unsigned long long p1 = xu[(2 * k4 + 1) * BSZ + l + 32];
#pragma unroll
        for (int i = 0; i < 4; i++) {
            ulonglong2 wv = wih[i][k4];
            acc[i][0] = ffma2(wv.x, a0, acc[i][0]);
            acc[i][0] = ffma2(wv.y, p0, acc[i][0]);
            acc[i][1] = ffma2(wv.x, a1, acc[i][1]);
            acc[i][1] = ffma2(wv.y, p1, acc[i][1]);
        }
    }

    const unsigned long long* hu = (const unsigned long long*)g_hT2f[rb];
#pragma unroll 4
    for (int k4 = 0; k4 < HID / 4; k4++) {
        unsigned long long a0 = hu[(2 * k4) * BSZ + l];
        unsigned long long a1 = hu[(2 * k4) * BSZ + l + 32];
        unsigned long long p0 = hu[(2 * k4 + 1) * BSZ + l];
        unsigned long long p1 = hu[(2 * k4 + 1) * BSZ + l + 32];
#pragma unroll
        for (int i = 0; i < 4; i++) {
            ulonglong2 wv = whh[i][k4];
            acc[i][0] = ffma2(wv.x, a0, acc[i][0]);
            acc[i][0] = ffma2(wv.y, p0, acc[i][0]);
            acc[i][1] = ffma2(wv.x, a1, acc[i][1]);
            acc[i][1] = ffma2(wv.y, p1, acc[i][1]);
        }
    }

    __shared__ float sg[32][BSZ];
#pragma unroll
    for (int i = 0; i < 4; i++) {
        float bias = __ldg(&b_ih[j[i]]) + __ldg(&b_hh[j[i]]);
        float2 f0 = u2f(acc[i][0]);
        float2 f1 = u2f(acc[i][1]);
        int cl = w * 4 + i;
        sg[cl][l]      = f0.x + f0.y + bias;
        sg[cl][l + 32] = f1.x + f1.y + bias;
    }
    __syncthreads();

    float* hOut = g_hT2f[rb ^ 1];
    for (int e = tid; e < 8 * BSZ; e += 256) {
        int b = e & 63, uo = e >> 6;
        float iv = sg[uo][b];
        float fv = sg[8 + uo][b];
        float gv = sg[16 + uo][b];
        float ov = sg[24 + uo][b];
        int u = u0 + uo;
        float cO = g_c[u * BSZ + b];
        float cN = sigm(fv) * cO + sigm(iv) * tanhf(gv);
        float hN = sigm(ov) * tanhf(cN);
        g_c[u * BSZ + b] = cN;
        hOut[((u >> 1) * BSZ + b) * 2 + (u & 1)] = hN;
    }
}

// ---------------------------------------------------------------------------
// LOGITS: logits = h @ out_W^T + out_b (64 x 32000). smem-staged GEMM:
// weights+h chunks copied coalesced into smem, compute via LDS. Warp owns
// 8 cols x 2 batch lanes (16 u64 f32x2 accumulators). Also:
//  - prologue: subtract lse[t-1] from previous step's output slice (fused sub)
//  - epilogue: raw logits -> out slice t, exp-sum partials, packed argmax
// ---------------------------------------------------------------------------
__global__ void __launch_bounds__(256, 2)
k_logits(const float* __restrict__ out_W, const float* __restrict__ out_b,
         int hb, float* __restrict__ out, int t) {
    __shared__ float sW[COLS_B * 64];                 // 64 cols x 64 k  (16KB)
    __shared__ float sH[64 * BSZ];                    // 64 k x 64 b     (16KB)
    __shared__ float s_sum[8][BSZ];
    __shared__ unsigned long long s_max[8][BSZ];

    int tid = threadIdx.x, w = tid >> 5, l = tid & 31;
    int colBase = blockIdx.x * COLS_B;
    int colW = colBase + w * COLS_W;

    // ---- fused: out[:, t-1, colBase:+64] -= lse  (overlaps with staging) ----
    if (t > 0) {
#pragma unroll
        for (int i = 0; i < 4; i++) {
            int f = tid + i * 256;
            int row = f >> 4, c4 = f & 15;
            float lse = __ldg(&g_lse[row]);
            float4* p = (float4*)(out + ((size_t)row * STEPS + (t - 1)) * VQ
                                  + colBase + c4 * 4);
            float4 r = *p;
            r.x -= lse; r.y -= lse; r.z -= lse; r.w -= lse;
            *p = r;
        }
    }

    unsigned long long acc0[COLS_W], acc1[COLS_W];
#pragma unroll
    for (int c = 0; c < COLS_W; c++) { acc0[c] = 0ull; acc1[c] = 0ull; }

    const float* hsrc = g_hT2f[hb];

    for (int ck = 0; ck < 8; ck++) {
        __syncthreads();
        // stage weights: 64 rows x 64 k floats (coalesced float4)
        {
            const size_t kof = (size_t)ck * 64;
#pragma unroll
            for (int i = 0; i < 4; i++) {
                int f = tid + i * 256;          // 1024 float4
                int row = f >> 4, k4o = f & 15;
                *(float4*)&sW[row * 64 + k4o * 4] =
                    *(const float4*)(out_W + (size_t)(colBase + row) * HID + kof + k4o * 4);
            }
        }
        // stage h: 32 pairs x 64 b = 4096 contiguous floats
        {
            const float4* src = (const float4*)(hsrc + ck * 4096);
            float4* dst = (float4*)sH;
#pragma unroll
            for (int i = 0; i < 4; i++) dst[tid + i * 256] = src[tid + i * 256];
        }
        __syncthreads();

        const unsigned long long* sHu = (const unsigned long long*)sH;
#pragma unroll 4
        for (int kk = 0; kk < 16; kk++) {
            unsigned long long a0 = sHu[(2 * kk) * BSZ + l];
            unsigned long long a1 = sHu[(2 * kk) * BSZ + l + 32];
            unsigned long long p0 = sHu[(2 * kk + 1) * BSZ + l];
            unsigned long long p1 = sHu[(2 * kk + 1) * BSZ + l + 32];
#pragma unroll
            for (int c = 0; c < COLS_W; c++) {
                ulonglong2 wv = *(const ulonglong2*)&sW[(w * COLS_W + c) * 64 + kk * 4];
                acc0[c] = ffma2(wv.x, a0, acc0[c]);
                acc0[c] = ffma2(wv.y, p0, acc0[c]);
                acc1[c] = ffma2(wv.x, a1, acc1[c]);
                acc1[c] = ffma2(wv.y, p1, acc1[c]);
            }
        }
    }

    int b0 = l, b1 = l + 32;
    float r0[COLS_W], r1[COLS_W];
    float es0 = 0.0f, es1 = 0.0f;
    unsigned long long m0 = 0ull, m1 = 0ull;
#pragma unroll
    for (int c = 0; c < COLS_W; c++) {
        float bias = __ldg(&out_b[colW + c]);
        float2 f0 = u2f(acc0[c]);
        float2 f1 = u2f(acc1[c]);
        r0[c] = f0.x + f0.y + bias;
        r1[c] = f1.x + f1.y + bias;
        es0 += __expf(r0[c]);
        es1 += __expf(r1[c]);
        unsigned long long q0 = packmax(r0[c], colW + c);
        unsigned long long q1 = packmax(r1[c], colW + c);
        m0 = (q0 > m0) ? q0 : m0;
        m1 = (q1 > m1) ? q1 : m1;
    }

    float* o0 = out + ((size_t)b0 * STEPS + t) * VQ + colW;
    float* o1 = out + ((size_t)b1 * STEPS + t) * VQ + colW;
    *(float4*)(o0)     = make_float4(r0[0], r0[1], r0[2], r0[3]);
    *(float4*)(o0 + 4) = make_float4(r0[4], r0[5], r0[6], r0[7]);
    *(float4*)(o1)     = make_float4(r1[0], r1[1], r1[2], r1[3]);
    *(float4*)(o1 + 4) = make_float4(r1[4], r1[5], r1[6], r1[7]);

    s_sum[w][b0] = es0; s_sum[w][b1] = es1;
    s_max[w][b0] = m0;  s_max[w][b1] = m1;
    __syncthreads();

    if (tid < BSZ) {
        float s = 0.0f;
        unsigned long long m = 0ull;
#pragma unroll
        for (int ww = 0; ww < 8; ww++) {
            s += s_sum[ww][tid];
            unsigned long long q = s_max[ww][tid];
            m = (q > m) ? q : m;
        }
        g_psum[tid * 512 + blockIdx.x] = s;
        atomicMax(&g_amax[tid], m);
    }
}

// ---------------------------------------------------------------------------
// REDUCE + EMBED: one block per batch row. lse = log(sum of 500 partials);
// next token from packed argmax -> qix_to_aix -> relu(emb[next]) into xT2.
// ---------------------------------------------------------------------------
__global__ void k_reduce(const float* __restrict__ emb, const int* __restrict__ qix) {
    __shared__ float sred[8];
    __shared__ int s_nidx;
    int b = blockIdx.x, tid = threadIdx.x, w = tid >> 5, l = tid & 31;

    float s = 0.0f;
    for (int i = tid; i < NBLK_L; i += 256) s += g_psum[b * 512 + i];
#pragma unroll
    for (int off = 16; off > 0; off >>= 1)
        s += __shfl_xor_sync(0xFFFFFFFFu, s, off);
    if (l == 0) sred[w] = s;
    __syncthreads();

    if (tid == 0) {
        float tot = 0.0f;
#pragma unroll
        for (int ww = 0; ww < 8; ww++) tot += sred[ww];
        g_lse[b] = logf(tot);
        unsigned long long m = g_amax[b];
        int col = (int)(0xFFFFFFFFu - (unsigned)(m & 0xFFFFFFFFull));
        s_nidx = __ldg(&qix[col]);
        g_amax[b] = 0ull;
    }
    __syncthreads();

    int nidx = s_nidx;
    for (int e = tid; e < EMBD; e += 256) {
        float x = __ldg(&emb[(size_t)nidx * EMBD + e]);
        g_xT2f[((e >> 1) * BSZ + b) * 2 + (e & 1)] = fmaxf(x, 0.0f);
    }
}

// ---------------------------------------------------------------------------
// SUB (tail only, t = 32): out[b][t][:] -= lse[b]
// ---------------------------------------------------------------------------
__global__ void k_sub(float* __restrict__ out, int t) {
    int gid = blockIdx.x * 256 + threadIdx.x;
    int idx = gid * 4;
    int b = idx / VQ;
    int v = idx - b * VQ;
    float lse = __ldg(&g_lse[b]);
    float4* p = (float4*)(out + ((size_t)b * STEPS + t) * VQ + v);
    float4 r = *p;
    r.x -= lse; r.y -= lse; r.z -= lse; r.w -= lse;
    *p = r;
}

// ---------------------------------------------------------------------------
// launch: init + 33 x (cell -> logits(+fused sub of t-1) -> reduce) + tail sub
// ---------------------------------------------------------------------------
extern "C" void kernel_launch(void* const* d_in, const int* in_sizes, int n_in,
                              void* d_out, int out_size) {
    (void)in_sizes; (void)n_in; (void)out_size;
    const float* q_att = (const float*)d_in[1];
    const float* emb   = (const float*)d_in[2];
    const float* W_ih  = (const float*)d_in[3];
    const float* W_hh  = (const float*)d_in[4];
    const float* b_ih  = (const float*)d_in[5];
    const float* b_hh  = (const float*)d_in[6];
    const float* out_W = (const float*)d_in[7];
    const float* out_b = (const float*)d_in[8];
    const int*   qix   = (const int*)d_in[9];
    float* out = (float*)d_out;

    int initWork = 2 * BSZ * HID + BSZ * EMBD + BSZ;
    k_init<<<(initWork + 255) / 256, 256>>>(q_att, emb, qix);

    for (int t = 0; t < STEPS; t++) {
        int rb = t & 1;
        k_cell<<<64, 256>>>(W_ih, W_hh, b_ih, b_hh, rb);
        k_logits<<<NBLK_L, 256>>>(out_W, out_b, rb ^ 1, out, t);
        k_reduce<<<BSZ, 256>>>(emb, qix);
    }
    k_sub<<<(BSZ * VQ / 4 + 255) / 256, 256>>>(out, STEPS - 1);
}